// round 10
// baseline (speedup 1.0000x reference)
#include <cuda_runtime.h>
#include <cuda_fp16.h>
#include <cstdint>
#include <math.h>

#define NMAX 100000

// ---------------- device scratch ----------------
__device__ float g_norm2[NMAX];
__device__ float g_hmsg[(size_t)NMAX * 64];
// fp16 weights: wih0[256x128] | whh0[256x64] | wih1 | whh1 | wih2 | whh2 (each 256x64)
__device__ __align__(16) __half g_w16[114688];

// ---------------- helpers ----------------
__device__ __forceinline__ void mma16(float* c, const unsigned* a, unsigned b0, unsigned b1) {
    asm volatile(
        "mma.sync.aligned.m16n8k16.row.col.f32.f16.f16.f32 "
        "{%0,%1,%2,%3}, {%4,%5,%6,%7}, {%8,%9}, {%0,%1,%2,%3};\n"
        : "+f"(c[0]), "+f"(c[1]), "+f"(c[2]), "+f"(c[3])
        : "r"(a[0]), "r"(a[1]), "r"(a[2]), "r"(a[3]), "r"(b0), "r"(b1));
}
__device__ __forceinline__ float tanha(float x) {
    float y;
    asm("tanh.approx.f32 %0, %1;" : "=f"(y) : "f"(x));
    return y;
}
__device__ __forceinline__ float fsig(float x) {          // sigmoid via 1-MUFU tanh
    return fmaf(0.5f, tanha(0.5f * x), 0.5f);
}
__device__ __forceinline__ float ftanh(float x) {         // accurate tanh (exp-based)
    float a = fabsf(x);
    float e = __expf(-2.0f * a);
    float t = __fdividef(1.0f - e, 1.0f + e);
    return copysignf(t, x);
}
__device__ __forceinline__ uint32_t smem_u32(const void* p) {
    uint32_t a;
    asm("{ .reg .u64 t; cvta.to.shared.u64 t, %1; cvt.u32.u64 %0, t; }" : "=r"(a) : "l"(p));
    return a;
}
__device__ __forceinline__ void cp16(uint32_t dst, const void* src) {
    asm volatile("cp.async.ca.shared.global [%0], [%1], 16;" :: "r"(dst), "l"(src) : "memory");
}
__device__ __forceinline__ void cp_commit() { asm volatile("cp.async.commit_group;" ::: "memory"); }
__device__ __forceinline__ void cp_wait1()  { asm volatile("cp.async.wait_group 1;" ::: "memory"); }
__device__ __forceinline__ void cp_wait0()  { asm volatile("cp.async.wait_group 0;" ::: "memory"); }
__device__ __forceinline__ unsigned h2u(__half2 h) { return *(unsigned*)&h; }

// ---------------- SMEM layout (bytes) ----------------
// A:    64 rows x 200 halves (stride 400B) -> 25600   (K=192 used)
// B:    2 buffers x (128 rows x 40 halves = 80B) -> 2 x 10240
// bsum: 256 floats -> 1024
#define A_OFF     0
#define B_OFF     25600
#define BBUF_SZ   10240
#define BSUM_OFF  (B_OFF + 2 * BBUF_SZ)        // 46080
#define SMEM_BYTES (BSUM_OFF + 1024)           // 47104

// fp16 weight offsets (in halves): {wih0, whh0, wih1, whh1, wih2, whh2}
__constant__ int c_woff[6] = {0, 32768, 49152, 65536, 81920, 98304};

// ---------------- kernel 0: convert all weights to fp16 ----------------
__global__ void wconv_kernel(const float* __restrict__ wih0, const float* __restrict__ whh0,
                             const float* __restrict__ wih1, const float* __restrict__ whh1,
                             const float* __restrict__ wih2, const float* __restrict__ whh2) {
    int i = blockIdx.x * blockDim.x + threadIdx.x;   // one float2 per thread
    if (i >= 57344) return;
    const float* srcs[6] = {wih0, whh0, wih1, whh1, wih2, whh2};
    int reg, off2;
    if (i < 16384) { reg = 0; off2 = i; }
    else { int t = i - 16384; reg = 1 + t / 8192; off2 = t - (reg - 1) * 8192; }
    float2 v = ((const float2*)srcs[reg])[off2];
    int base2 = (reg == 0) ? 0 : (16384 + (reg - 1) * 8192);
    ((__half2*)g_w16)[base2 + off2] = __floats2half2_rn(v.x, v.y);
}

// ---------------- kernel 1: per-row squared norms (16 lanes/row, float4) ----------------
__global__ void norm2_kernel(const float* __restrict__ feat, int n) {
    int row = (blockIdx.x * blockDim.x + threadIdx.x) >> 4;
    int sl = threadIdx.x & 15;
    if (row >= n) return;
    float4 v = *(const float4*)(feat + (size_t)row * 64 + sl * 4);
    float s = v.x * v.x + v.y * v.y + v.z * v.z + v.w * v.w;
    #pragma unroll
    for (int o = 8; o; o >>= 1) s += __shfl_down_sync(0xffffffffu, s, o, 16);
    if (sl == 0) g_norm2[row] = s;
}

// ---------------- kernel 2: argmax over neighbors + row gather ----------------
__global__ void gather_kernel(const float* __restrict__ feat, const int* __restrict__ src, int n) {
    int w = (blockIdx.x * blockDim.x + threadIdx.x) >> 5;
    int lane = threadIdx.x & 31;
    if (w >= n) return;
    int s = src[(size_t)w * 32 + lane];
    float bv = g_norm2[s];
    int bj = lane;
    #pragma unroll
    for (int o = 16; o; o >>= 1) {
        float ov = __shfl_down_sync(0xffffffffu, bv, o);
        int oj = __shfl_down_sync(0xffffffffu, bj, o);
        if (ov > bv || (ov == bv && oj < bj)) { bv = ov; bj = oj; }
    }
    bj = __shfl_sync(0xffffffffu, bj, 0);
    int bs = __shfl_sync(0xffffffffu, s, bj);
    float2 v = *(const float2*)(feat + (size_t)bs * 64 + lane * 2);
    *(float2*)(g_hmsg + (size_t)w * 64 + lane * 2) = v;
}

// ---------------- kernel 3: fused 3-layer LSTM (fp16 mma, M=64/CTA, 128 thr) ----------------
__global__ __launch_bounds__(128, 4) void lstm_kernel(
    const float* __restrict__ feature,
    const float* __restrict__ h0, const float* __restrict__ c0,
    const float* __restrict__ bih0, const float* __restrict__ bhh0,
    const float* __restrict__ bih1, const float* __restrict__ bhh1,
    const float* __restrict__ bih2, const float* __restrict__ bhh2,
    float* __restrict__ out, int n)
{
    extern __shared__ char smem[];
    unsigned* Xw = (unsigned*)(smem + A_OFF);       // A as 32-bit words (2 halves each)
    float* bsum = (float*)(smem + BSUM_OFF);
    const uint32_t sbase = smem_u32(smem);

    const int tid = threadIdx.x;
    const int lane = tid & 31;
    const int warp = tid >> 5;                      // 0..3
    const int wm = warp >> 1, wn = warp & 1;        // wm in {0,1}
    const int gid = lane >> 2, tig = lane & 3;
    const int m0w = wm * 32;
    const int m0 = blockIdx.x * 64;

    // staging role: thread -> one full 64B B-row per chunk
    const int rp = tid;                              // pass-local gate row 0..127
    const int gP0 = (rp >> 5) * 64 + (rp & 31);      // global W row for pass 0
    const uint32_t bdst_local = (uint32_t)(rp * 80);

    const float* bihA[3] = {bih0, bih1, bih2};
    const float* bhhA[3] = {bhh0, bhh1, bhh2};
    const size_t nd = (size_t)n * 64;
    float* out_hs = out + nd;
    float* out_cs = out + 4 * nd;

    // ---- hoisted prologue: stage (l=0,p=0) chunks 0,1 (wih0 k[0,32),[32,64)) ----
    {
        const __half* s0 = g_w16 + (size_t)gP0 * 128;
        uint32_t d0 = sbase + B_OFF + bdst_local;
        #pragma unroll
        for (int q = 0; q < 4; q++) cp16(d0 + q * 16, s0 + q * 8);
        cp_commit();
        const __half* s1 = s0 + 32;
        uint32_t d1 = sbase + B_OFF + BBUF_SZ + bdst_local;
        #pragma unroll
        for (int q = 0; q < 4; q++) cp16(d1 + q * 16, s1 + q * 8);
        cp_commit();
    }

    // ---- stage A for layer 0: [hmsg | feature | h0[0]], K=192, fp16 ----
    #pragma unroll 4
    for (int i = 0; i < 24; i++) {
        int idx = tid + (i << 7);
        int m = idx / 48, k4 = idx - m * 48;
        int node = m0 + m;
        float4 v = make_float4(0.f, 0.f, 0.f, 0.f);
        if (node < n) {
            size_t off = (size_t)node * 64;
            if (k4 < 16)      v = *(const float4*)(g_hmsg + off + k4 * 4);
            else if (k4 < 32) v = *(const float4*)(feature + off + (k4 - 16) * 4);
            else              v = *(const float4*)(h0 + off + (k4 - 32) * 4);
        }
        uint2 t;
        t.x = h2u(__floats2half2_rn(v.x, v.y));
        t.y = h2u(__floats2half2_rn(v.z, v.w));
        *(uint2*)(&Xw[m * 100 + k4 * 2]) = t;
    }

    for (int l = 0; l < 3; l++) {
        bsum[tid] = bihA[l][tid] + bhhA[l][tid];
        bsum[tid + 128] = bihA[l][tid + 128] + bhhA[l][tid + 128];
        const int ncg = (l == 0) ? 6 : 4;

        for (int p = 0; p < 2; p++) {
            const int grow = gP0 + p * 32;

            if (!(l == 0 && p == 0)) {
                #pragma unroll 1
                for (int c = 0; c < 2; c++) {
                    const __half* wp; int rs, ko;
                    if (l == 0) { wp = g_w16 + c_woff[0]; rs = 128; ko = c * 32; }
                    else {
                        int reg = (c < 2) ? (2 * l) : (2 * l + 1);
                        wp = g_w16 + c_woff[reg]; rs = 64; ko = (c & 1) * 32;
                    }
                    const __half* src = wp + (size_t)grow * rs + ko;
                    uint32_t dst = sbase + B_OFF + (c & 1) * BBUF_SZ + bdst_local;
                    #pragma unroll
                    for (int q = 0; q < 4; q++) cp16(dst + q * 16, src + q * 8);
                    cp_commit();
                }
            }

            float acc[2][8][4];
            #pragma unroll
            for (int mf = 0; mf < 2; mf++)
                #pragma unroll
                for (int f = 0; f < 8; f++)
                    #pragma unroll
                    for (int q = 0; q < 4; q++) acc[mf][f][q] = 0.f;

            #pragma unroll 1
            for (int c = 0; c < ncg; c++) {
                if (c < ncg - 1) cp_wait1(); else cp_wait0();
                __syncthreads();

                const unsigned* Bw = (const unsigned*)(smem + B_OFF + (c & 1) * BBUF_SZ);
                const int kw = c * 16;                 // chunk base in words (32 halves)
                #pragma unroll
                for (int ks = 0; ks < 2; ks++) {
                    const int w0 = kw + ks * 8 + tig;
                    unsigned a[2][4];
                    #pragma unroll
                    for (int mf = 0; mf < 2; mf++) {
                        int r = m0w + mf * 16 + gid;
                        a[mf][0] = Xw[r * 100 + w0];
                        a[mf][1] = Xw[(r + 8) * 100 + w0];
                        a[mf][2] = Xw[r * 100 + w0 + 4];
                        a[mf][3] = Xw[(r + 8) * 100 + w0 + 4];
                    }
                    const int bw0 = ks * 8 + tig;
                    #pragma unroll
                    for (int f = 0; f < 8; f++) {
                        int nc = (f >> 1) * 32 + wn * 16 + (f & 1) * 8 + gid;
                        unsigned b0 = Bw[nc * 20 + bw0];
                        unsigned b1 = Bw[nc * 20 + bw0 + 4];
                        mma16(acc[0][f], a[0], b0, b1);
                        mma16(acc[1][f], a[1], b0, b1);
                    }
                }
                __syncthreads();

                // re-stage chunk c+2 into buffer (c+2)&1
                int c2 = c + 2;
                if (c2 < ncg) {
                    const __half* wp; int rs, ko;
                    if (l == 0) {
                        if (c2 < 4) { wp = g_w16 + c_woff[0]; rs = 128; ko = c2 * 32; }
                        else        { wp = g_w16 + c_woff[1]; rs = 64;  ko = (c2 - 4) * 32; }
                    } else {
                        int reg = (c2 < 2) ? (2 * l) : (2 * l + 1);
                        wp = g_w16 + c_woff[reg]; rs = 64; ko = (c2 & 1) * 32;
                    }
                    const __half* src = wp + (size_t)grow * rs + ko;
                    uint32_t dst = sbase + B_OFF + (c2 & 1) * BBUF_SZ + bdst_local;
                    #pragma unroll
                    for (int q = 0; q < 4; q++) cp16(dst + q * 16, src + q * 8);
                    cp_commit();
                }
            }

            // ---------------- epilogue for this pass ----------------
            {
                const float* cg = c0 + (size_t)l * nd;
                const float* h0n = h0 + (size_t)(l + 1) * nd;
                float* hs_l = out_hs + (size_t)l * nd;
                float* cs_l = out_cs + (size_t)l * nd;

                #pragma unroll
                for (int mf = 0; mf < 2; mf++)
                    #pragma unroll
                    for (int jf = 0; jf < 2; jf++) {
                        const int d0 = p * 32 + wn * 16 + jf * 8 + 2 * tig;
                        #pragma unroll
                        for (int rh = 0; rh < 2; rh++) {
                            const int row = m0w + mf * 16 + gid + rh * 8;
                            const int node = m0 + row;
                            const bool valid = node < n;
                            const size_t noff = (size_t)node * 64;
                            float2 cp2 = make_float2(0.f, 0.f);
                            if (valid) cp2 = *(const float2*)(cg + noff + d0);
                            float hv[2], cv[2];
                            #pragma unroll
                            for (int q = 0; q < 2; q++) {
                                const int pp = rh * 2 + q;
                                const int d = d0 + q;
                                float iv = acc[mf][0 + jf][pp] + bsum[d];
                                float fv = acc[mf][2 + jf][pp] + bsum[64 + d];
                                float gv = acc[mf][4 + jf][pp] + bsum[128 + d];
                                float ov = acc[mf][6 + jf][pp] + bsum[192 + d];
                                float cprev = q ? cp2.y : cp2.x;
                                float cn = fsig(fv) * cprev + fsig(iv) * ftanh(gv);
                                hv[q] = fsig(ov) * ftanh(cn);
                                cv[q] = cn;
                            }
                            if (valid) {
                                *(float2*)(hs_l + noff + d0) = make_float2(hv[0], hv[1]);
                                *(float2*)(cs_l + noff + d0) = make_float2(cv[0], cv[1]);
                                if (l == 2) *(float2*)(out + noff + d0) = make_float2(hv[0], hv[1]);
                            }
                            // A rebuild only after the layer's final pass
                            if (l < 2 && p == 1) {
                                Xw[row * 100 + (d0 >> 1)] = h2u(__floats2half2_rn(hv[0], hv[1]));
                                float2 hh = make_float2(0.f, 0.f);
                                if (valid) hh = *(const float2*)(h0n + noff + d0);
                                Xw[row * 100 + 32 + (d0 >> 1)] = h2u(__floats2half2_rn(hh.x, hh.y));
                                // pass-0 columns: reload h from global (CTA-coherent after syncs)
                                const int dp = d0 - 32;
                                float2 hp = make_float2(0.f, 0.f), h2v = make_float2(0.f, 0.f);
                                if (valid) {
                                    hp = *(const float2*)(hs_l + noff + dp);
                                    h2v = *(const float2*)(h0n + noff + dp);
                                }
                                Xw[row * 100 + (dp >> 1)]      = h2u(__floats2half2_rn(hp.x, hp.y));
                                Xw[row * 100 + 32 + (dp >> 1)] = h2u(__floats2half2_rn(h2v.x, h2v.y));
                            }
                        }
                    }
                __syncthreads();
            }
        }
    }
}

// ---------------- launch ----------------
extern "C" void kernel_launch(void* const* d_in, const int* in_sizes, int n_in,
                              void* d_out, int out_size) {
    const float* feature = (const float*)d_in[0];
    const int* src       = (const int*)d_in[1];
    const float* h0      = (const float*)d_in[2];
    const float* c0      = (const float*)d_in[3];
    const float* wih0    = (const float*)d_in[4];
    const float* whh0    = (const float*)d_in[5];
    const float* bih0    = (const float*)d_in[6];
    const float* bhh0    = (const float*)d_in[7];
    const float* wih1    = (const float*)d_in[8];
    const float* whh1    = (const float*)d_in[9];
    const float* bih1    = (const float*)d_in[10];
    const float* bhh1    = (const float*)d_in[11];
    const float* wih2    = (const float*)d_in[12];
    const float* whh2    = (const float*)d_in[13];
    const float* bih2    = (const float*)d_in[14];
    const float* bhh2    = (const float*)d_in[15];
    float* out = (float*)d_out;

    int n = in_sizes[0] / 64;

    cudaFuncSetAttribute(lstm_kernel, cudaFuncAttributeMaxDynamicSharedMemorySize, SMEM_BYTES);

    wconv_kernel<<<224, 256>>>(wih0, whh0, wih1, whh1, wih2, whh2);

    int nblocks = (n * 16 + 255) / 256;
    norm2_kernel<<<nblocks, 256>>>(feature, n);
    int wblocks = (n + 7) / 8;
    gather_kernel<<<wblocks, 256>>>(feature, src, n);

    int lblocks = (n + 63) / 64;
    lstm_kernel<<<lblocks, 128, SMEM_BYTES>>>(
        feature, h0, c0,
        bih0, bhh0, bih1, bhh1, bih2, bhh2,
        out, n);
}

// round 11
// speedup vs baseline: 1.0547x; 1.0547x over previous
#include <cuda_runtime.h>
#include <cuda_fp16.h>
#include <cstdint>
#include <math.h>

#define NMAX 100000

// ---------------- device scratch ----------------
__device__ float g_norm2[NMAX];
__device__ float g_hmsg[(size_t)NMAX * 64];
// permuted fp16 weights: rows reordered so each pass's 64 rows are
// [ (i,f) interleaved dims | (g,o) interleaved dims ] for dims [16p,16p+16)
__device__ __align__(16) __half g_w16[114688];

// ---------------- helpers ----------------
__device__ __forceinline__ void mma16(float* c, const unsigned* a, unsigned b0, unsigned b1) {
    asm volatile(
        "mma.sync.aligned.m16n8k16.row.col.f32.f16.f16.f32 "
        "{%0,%1,%2,%3}, {%4,%5,%6,%7}, {%8,%9}, {%0,%1,%2,%3};\n"
        : "+f"(c[0]), "+f"(c[1]), "+f"(c[2]), "+f"(c[3])
        : "r"(a[0]), "r"(a[1]), "r"(a[2]), "r"(a[3]), "r"(b0), "r"(b1));
}
__device__ __forceinline__ float tanha(float x) {
    float y;
    asm("tanh.approx.f32 %0, %1;" : "=f"(y) : "f"(x));
    return y;
}
__device__ __forceinline__ float fsig(float x) {
    return fmaf(0.5f, tanha(0.5f * x), 0.5f);
}
__device__ __forceinline__ float ftanh(float x) {
    float a = fabsf(x);
    float e = __expf(-2.0f * a);
    float t = __fdividef(1.0f - e, 1.0f + e);
    return copysignf(t, x);
}
__device__ __forceinline__ uint32_t smem_u32(const void* p) {
    uint32_t a;
    asm("{ .reg .u64 t; cvta.to.shared.u64 t, %1; cvt.u32.u64 %0, t; }" : "=r"(a) : "l"(p));
    return a;
}
__device__ __forceinline__ void cp16(uint32_t dst, const void* src) {
    asm volatile("cp.async.ca.shared.global [%0], [%1], 16;" :: "r"(dst), "l"(src) : "memory");
}
__device__ __forceinline__ void cp_commit() { asm volatile("cp.async.commit_group;" ::: "memory"); }
__device__ __forceinline__ void cp_wait1()  { asm volatile("cp.async.wait_group 1;" ::: "memory"); }
__device__ __forceinline__ void cp_wait0()  { asm volatile("cp.async.wait_group 0;" ::: "memory"); }
__device__ __forceinline__ unsigned h2u(__half2 h) { return *(unsigned*)&h; }

// ---------------- SMEM layout (bytes) ----------------
// A:    128 rows x 100 words (K=192 halves + pad)  -> 51200
// B:    2 buffers x (64 rows x 36 words)           -> 2 x 9216
// bsum: 256 floats                                 -> 1024
#define A_OFF     0
#define B_OFF     51200
#define BBUF_SZ   9216
#define BSUM_OFF  (B_OFF + 2 * BBUF_SZ)    // 69632
#define SMEM_BYTES (BSUM_OFF + 1024)       // 70656

// permuted-weight region offsets (halves): {wih0, whh0, wih1, whh1, wih2, whh2}
__constant__ int c_woff[6] = {0, 32768, 49152, 65536, 81920, 98304};

// ---------------- kernel 0: permute + convert weights to fp16 ----------------
// out row c (0..255): p=c>>6, cp=c&63, half=(cp>>5)&1, idx=cp&31,
//   dim d = 16p + (idx>>1), gate g = 2*half + (idx&1), orig row = g*64 + d
__global__ void wconv_kernel(const float* __restrict__ wih0, const float* __restrict__ whh0,
                             const float* __restrict__ wih1, const float* __restrict__ whh1,
                             const float* __restrict__ wih2, const float* __restrict__ whh2) {
    int i = blockIdx.x * blockDim.x + threadIdx.x;   // one float2 per thread
    if (i >= 57344) return;
    const float* srcs[6] = {wih0, whh0, wih1, whh1, wih2, whh2};
    int reg, off2;
    if (i < 16384) { reg = 0; off2 = i; }
    else { int t = i - 16384; reg = 1 + t / 8192; off2 = t - (reg - 1) * 8192; }
    int rs2 = (reg == 0) ? 64 : 32;                  // row length in float2
    int rowp = off2 / rs2, k2 = off2 - rowp * rs2;
    int p = rowp >> 6, cp = rowp & 63;
    int half = (cp >> 5) & 1, idx = cp & 31;
    int d = (p << 4) + (idx >> 1);
    int g = (half << 1) | (idx & 1);
    int orig = (g << 6) + d;
    float2 v = ((const float2*)srcs[reg])[orig * rs2 + k2];
    int base2 = (reg == 0) ? 0 : (16384 + (reg - 1) * 8192);
    ((__half2*)g_w16)[base2 + off2] = __floats2half2_rn(v.x, v.y);
}

// ---------------- kernel 1: per-row squared norms ----------------
__global__ void norm2_kernel(const float* __restrict__ feat, int n) {
    int row = (blockIdx.x * blockDim.x + threadIdx.x) >> 4;
    int sl = threadIdx.x & 15;
    if (row >= n) return;
    float4 v = *(const float4*)(feat + (size_t)row * 64 + sl * 4);
    float s = v.x * v.x + v.y * v.y + v.z * v.z + v.w * v.w;
    #pragma unroll
    for (int o = 8; o; o >>= 1) s += __shfl_down_sync(0xffffffffu, s, o, 16);
    if (sl == 0) g_norm2[row] = s;
}

// ---------------- kernel 2: argmax over neighbors + row gather ----------------
__global__ void gather_kernel(const float* __restrict__ feat, const int* __restrict__ src, int n) {
    int w = (blockIdx.x * blockDim.x + threadIdx.x) >> 5;
    int lane = threadIdx.x & 31;
    if (w >= n) return;
    int s = src[(size_t)w * 32 + lane];
    float bv = g_norm2[s];
    int bj = lane;
    #pragma unroll
    for (int o = 16; o; o >>= 1) {
        float ov = __shfl_down_sync(0xffffffffu, bv, o);
        int oj = __shfl_down_sync(0xffffffffu, bj, o);
        if (ov > bv || (ov == bv && oj < bj)) { bv = ov; bj = oj; }
    }
    bj = __shfl_sync(0xffffffffu, bj, 0);
    int bs = __shfl_sync(0xffffffffu, s, bj);
    float2 v = *(const float2*)(feat + (size_t)bs * 64 + lane * 2);
    *(float2*)(g_hmsg + (size_t)w * 64 + lane * 2) = v;
}

// ---------------- kernel 3: fused 3-layer LSTM, 512 thr, 16 acc/thread ----------------
__global__ __launch_bounds__(512, 2) void lstm_kernel(
    const float* __restrict__ feature,
    const float* __restrict__ h0, const float* __restrict__ c0,
    const float* __restrict__ bih0, const float* __restrict__ bhh0,
    const float* __restrict__ bih1, const float* __restrict__ bhh1,
    const float* __restrict__ bih2, const float* __restrict__ bhh2,
    float* __restrict__ out, int n)
{
    extern __shared__ char smem[];
    unsigned* Xw = (unsigned*)(smem + A_OFF);       // A words (half2)
    float* bsum = (float*)(smem + BSUM_OFF);
    const uint32_t sbase = smem_u32(smem);

    const int tid = threadIdx.x;
    const int lane = tid & 31;
    const int warp = tid >> 5;                      // 0..15
    const int wm = warp >> 2, ng = warp & 3;        // 4 M-groups x 4 N-groups
    const int gid = lane >> 2, tig = lane & 3;
    const int m0w = wm * 32;
    const int m0 = blockIdx.x * 128;

    // B staging: one 16B cp per thread per chunk (64 rows x 128B)
    const int srow = tid >> 3, s8 = tid & 7;
    const uint32_t bdst_local = (uint32_t)(srow * 144 + s8 * 16);

    const float* bihA[3] = {bih0, bih1, bih2};
    const float* bhhA[3] = {bhh0, bhh1, bhh2};
    const size_t nd = (size_t)n * 64;
    float* out_hs = out + nd;
    float* out_cs = out + 4 * nd;

    // ---- hoisted prologue: l=0,p=0 chunks 0,1 (wih0 rows [0,64), k [0,64),[64,128)) ----
    {
        const __half* s0 = g_w16 + (size_t)srow * 128 + s8 * 8;
        cp16(sbase + B_OFF + bdst_local, s0);
        cp_commit();
        cp16(sbase + B_OFF + BBUF_SZ + bdst_local, s0 + 64);
        cp_commit();
    }

    // ---- stage A for layer 0: [hmsg | feature | h0[0]], K=192 ----
    #pragma unroll 2
    for (int i = 0; i < 12; i++) {
        int idx = tid + (i << 9);
        int m = idx / 48, k4 = idx - m * 48;
        int node = m0 + m;
        float4 v = make_float4(0.f, 0.f, 0.f, 0.f);
        if (node < n) {
            size_t off = (size_t)node * 64;
            if (k4 < 16)      v = *(const float4*)(g_hmsg + off + k4 * 4);
            else if (k4 < 32) v = *(const float4*)(feature + off + (k4 - 16) * 4);
            else              v = *(const float4*)(h0 + off + (k4 - 32) * 4);
        }
        uint2 t;
        t.x = h2u(__floats2half2_rn(v.x, v.y));
        t.y = h2u(__floats2half2_rn(v.z, v.w));
        *(uint2*)(&Xw[m * 100 + k4 * 2]) = t;
    }

    for (int l = 0; l < 3; l++) {
        if (tid < 256) bsum[tid] = bihA[l][tid] + bhhA[l][tid];
        const int ncg = (l == 0) ? 3 : 2;           // k64 chunks

        for (int p = 0; p < 4; p++) {
            // prologue staging (skip l=0,p=0: hoisted)
            if (!(l == 0 && p == 0)) {
                #pragma unroll
                for (int c = 0; c < 2; c++) {
                    const __half* wp; int rs, ko;
                    if (l == 0) { wp = g_w16; rs = 128; ko = c * 64; }
                    else {
                        int reg = (c == 0) ? (2 * l) : (2 * l + 1);
                        wp = g_w16 + c_woff[reg]; rs = 64; ko = 0;
                    }
                    const __half* src = wp + (size_t)(p * 64 + srow) * rs + ko + s8 * 8;
                    cp16(sbase + B_OFF + c * BBUF_SZ + bdst_local, src);
                    cp_commit();
                }
            }

            float acc[2][2][4];
            #pragma unroll
            for (int mf = 0; mf < 2; mf++)
                #pragma unroll
                for (int h = 0; h < 2; h++)
                    #pragma unroll
                    for (int q = 0; q < 4; q++) acc[mf][h][q] = 0.f;

            #pragma unroll 1
            for (int c = 0; c < ncg; c++) {
                if (c < ncg - 1) cp_wait1(); else cp_wait0();
                __syncthreads();

                const unsigned* Bw = (const unsigned*)(smem + B_OFF + (c & 1) * BBUF_SZ);
                #pragma unroll
                for (int ks = 0; ks < 4; ks++) {
                    const int w0 = c * 32 + ks * 8 + tig;
                    unsigned a[2][4];
                    #pragma unroll
                    for (int mf = 0; mf < 2; mf++) {
                        int r = m0w + mf * 16 + gid;
                        a[mf][0] = Xw[r * 100 + w0];
                        a[mf][1] = Xw[(r + 8) * 100 + w0];
                        a[mf][2] = Xw[r * 100 + w0 + 4];
                        a[mf][3] = Xw[(r + 8) * 100 + w0 + 4];
                    }
                    const int kwB = ks * 8 + tig;
                    #pragma unroll
                    for (int h = 0; h < 2; h++) {
                        const int nc = h * 32 + 8 * ng + gid;
                        unsigned b0 = Bw[nc * 36 + kwB];
                        unsigned b1 = Bw[nc * 36 + kwB + 4];
                        mma16(acc[0][h], a[0], b0, b1);
                        mma16(acc[1][h], a[1], b0, b1);
                    }
                }
                __syncthreads();

                int c2 = c + 2;                     // only l=0: chunk 2 = whh0
                if (c2 < ncg) {
                    const __half* src = g_w16 + 32768 + (size_t)(p * 64 + srow) * 64 + s8 * 8;
                    cp16(sbase + B_OFF + (c2 & 1) * BBUF_SZ + bdst_local, src);
                    cp_commit();
                }
            }

            // ---------------- epilogue (no barrier needed for p<3) ----------------
            {
                const float* cg = c0 + (size_t)l * nd;
                float* hs_l = out_hs + (size_t)l * nd;
                float* cs_l = out_cs + (size_t)l * nd;
                const int d = p * 16 + 4 * ng + tig;    // this thread's output dim

                #pragma unroll
                for (int mf = 0; mf < 2; mf++)
                    #pragma unroll
                    for (int rh = 0; rh < 2; rh++) {
                        const int row = m0w + mf * 16 + gid + rh * 8;
                        const int node = m0 + row;
                        const bool valid = node < n;
                        const size_t noff = (size_t)node * 64;
                        float iv = acc[mf][0][2 * rh]     + bsum[d];
                        float fv = acc[mf][0][2 * rh + 1] + bsum[64 + d];
                        float gv = acc[mf][1][2 * rh]     + bsum[128 + d];
                        float ov = acc[mf][1][2 * rh + 1] + bsum[192 + d];
                        float cp = valid ? cg[noff + d] : 0.f;
                        float cn = fsig(fv) * cp + fsig(iv) * ftanh(gv);
                        float hn = fsig(ov) * ftanh(cn);
                        if (valid) {
                            hs_l[noff + d] = hn;
                            cs_l[noff + d] = cn;
                            if (l == 2) out[noff + d] = hn;
                        }
                    }
            }
        }

        // ---- layer end: rebuild A = [h_l | h0[l+1]] from global (coherent via L2) ----
        if (l < 2) {
            __syncthreads();   // all epilogue stores of this layer visible
            const float* hs_l = out_hs + (size_t)l * nd;
            const float* h0n = h0 + (size_t)(l + 1) * nd;
            #pragma unroll 2
            for (int i = 0; i < 8; i++) {
                int idx = tid + (i << 9);          // 4096 = 128 rows x 32 float4
                int m = idx >> 5, k4 = idx & 31;
                int node = m0 + m;
                float4 v = make_float4(0.f, 0.f, 0.f, 0.f);
                if (node < n) {
                    size_t off = (size_t)node * 64;
                    v = (k4 < 16) ? *(const float4*)(hs_l + off + k4 * 4)
                                  : *(const float4*)(h0n + off + (k4 - 16) * 4);
                }
                uint2 t;
                t.x = h2u(__floats2half2_rn(v.x, v.y));
                t.y = h2u(__floats2half2_rn(v.z, v.w));
                *(uint2*)(&Xw[m * 100 + k4 * 2]) = t;
            }
            // next layer's first chunk-loop __syncthreads orders these writes
        }
    }
}

// ---------------- launch ----------------
extern "C" void kernel_launch(void* const* d_in, const int* in_sizes, int n_in,
                              void* d_out, int out_size) {
    const float* feature = (const float*)d_in[0];
    const int* src       = (const int*)d_in[1];
    const float* h0      = (const float*)d_in[2];
    const float* c0      = (const float*)d_in[3];
    const float* wih0    = (const float*)d_in[4];
    const float* whh0    = (const float*)d_in[5];
    const float* bih0    = (const float*)d_in[6];
    const float* bhh0    = (const float*)d_in[7];
    const float* wih1    = (const float*)d_in[8];
    const float* whh1    = (const float*)d_in[9];
    const float* bih1    = (const float*)d_in[10];
    const float* bhh1    = (const float*)d_in[11];
    const float* wih2    = (const float*)d_in[12];
    const float* whh2    = (const float*)d_in[13];
    const float* bih2    = (const float*)d_in[14];
    const float* bhh2    = (const float*)d_in[15];
    float* out = (float*)d_out;

    int n = in_sizes[0] / 64;

    cudaFuncSetAttribute(lstm_kernel, cudaFuncAttributeMaxDynamicSharedMemorySize, SMEM_BYTES);

    wconv_kernel<<<224, 256>>>(wih0, whh0, wih1, whh1, wih2, whh2);

    int nblocks = (n * 16 + 255) / 256;
    norm2_kernel<<<nblocks, 256>>>(feature, n);
    int wblocks = (n + 7) / 8;
    gather_kernel<<<wblocks, 256>>>(feature, src, n);

    int lblocks = (n + 127) / 128;
    lstm_kernel<<<lblocks, 512, SMEM_BYTES>>>(
        feature, h0, c0,
        bih0, bhh0, bih1, bhh1, bih2, bhh2,
        out, n);
}

// round 12
// speedup vs baseline: 1.1163x; 1.0585x over previous
#include <cuda_runtime.h>
#include <cuda_fp16.h>
#include <cstdint>
#include <math.h>

#define NMAX 100000

// ---------------- device scratch ----------------
__device__ float g_norm2[NMAX];
__device__ float g_hmsg[(size_t)NMAX * 64];
// permuted fp16 weights: rows reordered so each pass's 64 rows are
// [ (i,f) interleaved dims | (g,o) interleaved dims ] for dims [16p,16p+16)
__device__ __align__(16) __half g_w16[114688];

// ---------------- helpers ----------------
__device__ __forceinline__ void mma16(float* c, const unsigned* a, unsigned b0, unsigned b1) {
    asm volatile(
        "mma.sync.aligned.m16n8k16.row.col.f32.f16.f16.f32 "
        "{%0,%1,%2,%3}, {%4,%5,%6,%7}, {%8,%9}, {%0,%1,%2,%3};\n"
        : "+f"(c[0]), "+f"(c[1]), "+f"(c[2]), "+f"(c[3])
        : "r"(a[0]), "r"(a[1]), "r"(a[2]), "r"(a[3]), "r"(b0), "r"(b1));
}
__device__ __forceinline__ void ldm4(unsigned* r, uint32_t addr) {
    asm volatile("ldmatrix.sync.aligned.m8n8.x4.shared.b16 {%0,%1,%2,%3}, [%4];"
                 : "=r"(r[0]), "=r"(r[1]), "=r"(r[2]), "=r"(r[3]) : "r"(addr));
}
__device__ __forceinline__ float tanha(float x) {
    float y;
    asm("tanh.approx.f32 %0, %1;" : "=f"(y) : "f"(x));
    return y;
}
__device__ __forceinline__ float fsig(float x) {
    return fmaf(0.5f, tanha(0.5f * x), 0.5f);
}
__device__ __forceinline__ float ftanh(float x) {
    float a = fabsf(x);
    float e = __expf(-2.0f * a);
    float t = __fdividef(1.0f - e, 1.0f + e);
    return copysignf(t, x);
}
__device__ __forceinline__ uint32_t smem_u32(const void* p) {
    uint32_t a;
    asm("{ .reg .u64 t; cvta.to.shared.u64 t, %1; cvt.u32.u64 %0, t; }" : "=r"(a) : "l"(p));
    return a;
}
__device__ __forceinline__ void cp16(uint32_t dst, const void* src) {
    asm volatile("cp.async.ca.shared.global [%0], [%1], 16;" :: "r"(dst), "l"(src) : "memory");
}
__device__ __forceinline__ void cp_commit() { asm volatile("cp.async.commit_group;" ::: "memory"); }
__device__ __forceinline__ void cp_wait0()  { asm volatile("cp.async.wait_group 0;" ::: "memory"); }
__device__ __forceinline__ unsigned h2u(__half2 h) { return *(unsigned*)&h; }

// ---------------- SMEM layout (bytes) ----------------
// A:    128 rows x 400B (K<=192 halves + pad)          -> 51200
// W:    2 buffers x (64 rows x 400B pass-block)        -> 2 x 25600
// bsum: 256 floats                                     -> 1024
#define A_OFF     0
#define W_OFF     51200
#define WBUF_SZ   25600
#define BSUM_OFF  (W_OFF + 2 * WBUF_SZ)    // 102400
#define SMEM_BYTES (BSUM_OFF + 1024)       // 103424

// permuted-weight region offsets (halves): {wih0, whh0, wih1, whh1, wih2, whh2}
__constant__ int c_woff[6] = {0, 32768, 49152, 65536, 81920, 98304};

// ---------------- kernel 0: permute + convert weights to fp16 ----------------
// out row c (0..255): p=c>>6, cp=c&63, half=(cp>>5)&1, idx=cp&31,
//   dim d = 16p + (idx>>1), gate g = 2*half + (idx&1), orig row = g*64 + d
__global__ void wconv_kernel(const float* __restrict__ wih0, const float* __restrict__ whh0,
                             const float* __restrict__ wih1, const float* __restrict__ whh1,
                             const float* __restrict__ wih2, const float* __restrict__ whh2) {
    int i = blockIdx.x * blockDim.x + threadIdx.x;   // one float2 per thread
    if (i >= 57344) return;
    const float* srcs[6] = {wih0, whh0, wih1, whh1, wih2, whh2};
    int reg, off2;
    if (i < 16384) { reg = 0; off2 = i; }
    else { int t = i - 16384; reg = 1 + t / 8192; off2 = t - (reg - 1) * 8192; }
    int rs2 = (reg == 0) ? 64 : 32;                  // row length in float2
    int rowp = off2 / rs2, k2 = off2 - rowp * rs2;
    int p = rowp >> 6, cp = rowp & 63;
    int half = (cp >> 5) & 1, idx = cp & 31;
    int d = (p << 4) + (idx >> 1);
    int g = (half << 1) | (idx & 1);
    int orig = (g << 6) + d;
    float2 v = ((const float2*)srcs[reg])[orig * rs2 + k2];
    int base2 = (reg == 0) ? 0 : (16384 + (reg - 1) * 8192);
    ((__half2*)g_w16)[base2 + off2] = __floats2half2_rn(v.x, v.y);
}

// ---------------- kernel 1: per-row squared norms ----------------
__global__ void norm2_kernel(const float* __restrict__ feat, int n) {
    int row = (blockIdx.x * blockDim.x + threadIdx.x) >> 4;
    int sl = threadIdx.x & 15;
    if (row >= n) return;
    float4 v = *(const float4*)(feat + (size_t)row * 64 + sl * 4);
    float s = v.x * v.x + v.y * v.y + v.z * v.z + v.w * v.w;
    #pragma unroll
    for (int o = 8; o; o >>= 1) s += __shfl_down_sync(0xffffffffu, s, o, 16);
    if (sl == 0) g_norm2[row] = s;
}

// ---------------- kernel 2: argmax over neighbors + row gather ----------------
__global__ void gather_kernel(const float* __restrict__ feat, const int* __restrict__ src, int n) {
    int w = (blockIdx.x * blockDim.x + threadIdx.x) >> 5;
    int lane = threadIdx.x & 31;
    if (w >= n) return;
    int s = src[(size_t)w * 32 + lane];
    float bv = g_norm2[s];
    int bj = lane;
    #pragma unroll
    for (int o = 16; o; o >>= 1) {
        float ov = __shfl_down_sync(0xffffffffu, bv, o);
        int oj = __shfl_down_sync(0xffffffffu, bj, o);
        if (ov > bv || (ov == bv && oj < bj)) { bv = ov; bj = oj; }
    }
    bj = __shfl_sync(0xffffffffu, bj, 0);
    int bs = __shfl_sync(0xffffffffu, s, bj);
    float2 v = *(const float2*)(feat + (size_t)bs * 64 + lane * 2);
    *(float2*)(g_hmsg + (size_t)w * 64 + lane * 2) = v;
}

// ---------------- pass-block staging (all K for 64 permuted gate rows) ----------------
// l=0 row: [wih0 128 halves | whh0 64 halves]; l>=1: [wih_l 64 | whh_l 64]
__device__ __forceinline__ void stage_block(int l, int p, uint32_t wdst, int tid) {
    if (l == 0) {
        #pragma unroll
        for (int it = 0; it < 2; it++) {
            int idx = tid + (it << 9);
            int rr = idx >> 4, kc = idx & 15;
            cp16(wdst + rr * 400 + kc * 16, g_w16 + (size_t)(p * 64 + rr) * 128 + kc * 8);
        }
        int rr = tid >> 3, kc = tid & 7;
        cp16(wdst + rr * 400 + 256 + kc * 16,
             g_w16 + 32768 + (size_t)(p * 64 + rr) * 64 + kc * 8);
    } else {
        int rr = tid >> 3, kc = tid & 7;
        cp16(wdst + rr * 400 + kc * 16,
             g_w16 + c_woff[2 * l] + (size_t)(p * 64 + rr) * 64 + kc * 8);
        cp16(wdst + rr * 400 + 128 + kc * 16,
             g_w16 + c_woff[2 * l + 1] + (size_t)(p * 64 + rr) * 64 + kc * 8);
    }
}

// ---------------- kernel 3: fused 3-layer LSTM, 512 thr, ldmatrix, 14 barriers ----------------
__global__ __launch_bounds__(512, 2) void lstm_kernel(
    const float* __restrict__ feature,
    const float* __restrict__ h0, const float* __restrict__ c0,
    const float* __restrict__ bih0, const float* __restrict__ bhh0,
    const float* __restrict__ bih1, const float* __restrict__ bhh1,
    const float* __restrict__ bih2, const float* __restrict__ bhh2,
    float* __restrict__ out, int n)
{
    extern __shared__ char smem[];
    unsigned* Xw = (unsigned*)(smem + A_OFF);       // A words (half2), row stride 100 words
    float* bsum = (float*)(smem + BSUM_OFF);
    const uint32_t sbase = smem_u32(smem);

    const int tid = threadIdx.x;
    const int lane = tid & 31;
    const int warp = tid >> 5;                      // 0..15
    const int wm = warp >> 2, ng = warp & 3;        // 4 M-groups x 4 N-groups
    const int gid = lane >> 2, tig = lane & 3;
    const int m0w = wm * 32;
    const int m0 = blockIdx.x * 128;

    // ldmatrix lane addresses
    const int lt = lane >> 3, lr = lane & 7;        // tile, row-in-tile
    // A tiles: {m0 klo, m8 klo, m0 khi, m8 khi}
    const uint32_t aAddr0 = sbase + A_OFF
        + (uint32_t)((m0w + ((lt & 1) << 3) + lr) * 400 + ((lt >> 1) << 4));
    const uint32_t aAddr1 = aAddr0 + 16 * 400;
    // B tiles: {(i,f) klo, (i,f) khi, (g,o) klo, (g,o) khi}; rows (lt>>1)*32 + 8ng + lr
    const uint32_t bLane = (uint32_t)((((lt >> 1) << 5) + (ng << 3) + lr) * 400
                                      + ((lt & 1) << 4));

    const float* bihA[3] = {bih0, bih1, bih2};
    const float* bhhA[3] = {bhh0, bhh1, bhh2};
    const size_t nd = (size_t)n * 64;
    float* out_hs = out + nd;
    float* out_cs = out + 4 * nd;

    // ---- prologue: stage block (0,0); A tile; bias ----
    stage_block(0, 0, sbase + W_OFF, tid);
    cp_commit();
    if (tid < 256) bsum[tid] = bih0[tid] + bhh0[tid];

    #pragma unroll 2
    for (int i = 0; i < 12; i++) {
        int idx = tid + (i << 9);
        int m = idx / 48, k4 = idx - m * 48;
        int node = m0 + m;
        float4 v = make_float4(0.f, 0.f, 0.f, 0.f);
        if (node < n) {
            size_t off = (size_t)node * 64;
            if (k4 < 16)      v = *(const float4*)(g_hmsg + off + k4 * 4);
            else if (k4 < 32) v = *(const float4*)(feature + off + (k4 - 16) * 4);
            else              v = *(const float4*)(h0 + off + (k4 - 32) * 4);
        }
        uint2 t;
        t.x = h2u(__floats2half2_rn(v.x, v.y));
        t.y = h2u(__floats2half2_rn(v.z, v.w));
        *(uint2*)(&Xw[m * 100 + k4 * 2]) = t;
    }

    int buf = 0;
    for (int l = 0; l < 3; l++) {
        const int nks = (l == 0) ? 12 : 8;

        for (int p = 0; p < 4; p++) {
            cp_wait0();
            __syncthreads();    // block p visible; all warps done with buf^1

            // stage next block into the other buffer
            if (!(l == 2 && p == 3)) {
                int nl = (p < 3) ? l : l + 1;
                int np = (p < 3) ? p + 1 : 0;
                stage_block(nl, np, sbase + W_OFF + (buf ^ 1) * WBUF_SZ, tid);
                cp_commit();
            }

            float acc[2][2][4];
            #pragma unroll
            for (int mf = 0; mf < 2; mf++)
                #pragma unroll
                for (int h = 0; h < 2; h++)
                    #pragma unroll
                    for (int q = 0; q < 4; q++) acc[mf][h][q] = 0.f;

            const uint32_t wb = sbase + W_OFF + buf * WBUF_SZ + bLane;
            #pragma unroll 4
            for (int ks = 0; ks < nks; ks++) {
                unsigned a0[4], a1[4], bq[4];
                ldm4(a0, aAddr0 + ks * 32);
                ldm4(a1, aAddr1 + ks * 32);
                ldm4(bq, wb + ks * 32);
                mma16(acc[0][0], a0, bq[0], bq[1]);
                mma16(acc[1][0], a1, bq[0], bq[1]);
                mma16(acc[0][1], a0, bq[2], bq[3]);
                mma16(acc[1][1], a1, bq[2], bq[3]);
            }
            buf ^= 1;

            // ---- epilogue for this pass (no barrier) ----
            {
                const float* cg = c0 + (size_t)l * nd;
                float* hs_l = out_hs + (size_t)l * nd;
                float* cs_l = out_cs + (size_t)l * nd;
                const int d = p * 16 + 4 * ng + tig;    // this thread's output dim

                #pragma unroll
                for (int mf = 0; mf < 2; mf++)
                    #pragma unroll
                    for (int rh = 0; rh < 2; rh++) {
                        const int row = m0w + mf * 16 + gid + rh * 8;
                        const int node = m0 + row;
                        const bool valid = node < n;
                        const size_t noff = (size_t)node * 64;
                        float iv = acc[mf][0][2 * rh]     + bsum[d];
                        float fv = acc[mf][0][2 * rh + 1] + bsum[64 + d];
                        float gv = acc[mf][1][2 * rh]     + bsum[128 + d];
                        float ov = acc[mf][1][2 * rh + 1] + bsum[192 + d];
                        float cp = valid ? cg[noff + d] : 0.f;
                        float cn = fsig(fv) * cp + fsig(iv) * ftanh(gv);
                        float hn = fsig(ov) * ftanh(cn);
                        if (valid) {
                            hs_l[noff + d] = hn;
                            cs_l[noff + d] = cn;
                            if (l == 2) out[noff + d] = hn;
                        }
                    }
            }
        }

        // ---- layer end: rebuild A = [h_l | h0[l+1]] ; bias for next layer ----
        if (l < 2) {
            __syncthreads();   // all MMA reads of Xw + epilogue stores done
            const float* hs_l = out_hs + (size_t)l * nd;
            const float* h0n = h0 + (size_t)(l + 1) * nd;
            #pragma unroll 2
            for (int i = 0; i < 8; i++) {
                int idx = tid + (i << 9);          // 4096 = 128 rows x 32 float4
                int m = idx >> 5, k4 = idx & 31;
                int node = m0 + m;
                float4 v = make_float4(0.f, 0.f, 0.f, 0.f);
                if (node < n) {
                    size_t off = (size_t)node * 64;
                    v = (k4 < 16) ? *(const float4*)(hs_l + off + k4 * 4)
                                  : *(const float4*)(h0n + off + (k4 - 16) * 4);
                }
                uint2 t;
                t.x = h2u(__floats2half2_rn(v.x, v.y));
                t.y = h2u(__floats2half2_rn(v.z, v.w));
                *(uint2*)(&Xw[m * 100 + k4 * 2]) = t;
            }
            if (tid < 256) bsum[tid] = bihA[l + 1][tid] + bhhA[l + 1][tid];
            // next pass-0 __syncthreads orders these writes before MMA reads
        }
    }
}

// ---------------- launch ----------------
extern "C" void kernel_launch(void* const* d_in, const int* in_sizes, int n_in,
                              void* d_out, int out_size) {
    const float* feature = (const float*)d_in[0];
    const int* src       = (const int*)d_in[1];
    const float* h0      = (const float*)d_in[2];
    const float* c0      = (const float*)d_in[3];
    const float* wih0    = (const float*)d_in[4];
    const float* whh0    = (const float*)d_in[5];
    const float* bih0    = (const float*)d_in[6];
    const float* bhh0    = (const float*)d_in[7];
    const float* wih1    = (const float*)d_in[8];
    const float* whh1    = (const float*)d_in[9];
    const float* bih1    = (const float*)d_in[10];
    const float* bhh1    = (const float*)d_in[11];
    const float* wih2    = (const float*)d_in[12];
    const float* whh2    = (const float*)d_in[13];
    const float* bih2    = (const float*)d_in[14];
    const float* bhh2    = (const float*)d_in[15];
    float* out = (float*)d_out;

    int n = in_sizes[0] / 64;

    cudaFuncSetAttribute(lstm_kernel, cudaFuncAttributeMaxDynamicSharedMemorySize, SMEM_BYTES);

    wconv_kernel<<<224, 256>>>(wih0, whh0, wih1, whh1, wih2, whh2);

    int nblocks = (n * 16 + 255) / 256;
    norm2_kernel<<<nblocks, 256>>>(feature, n);
    int wblocks = (n + 7) / 8;
    gather_kernel<<<wblocks, 256>>>(feature, src, n);

    int lblocks = (n + 127) / 128;
    lstm_kernel<<<lblocks, 512, SMEM_BYTES>>>(
        feature, h0, c0,
        bih0, bhh0, bih1, bhh1, bih2, bhh2,
        out, n);
}

// round 13
// speedup vs baseline: 1.2483x; 1.1182x over previous
#include <cuda_runtime.h>
#include <cuda_fp16.h>
#include <cstdint>
#include <math.h>

#define NMAX 100000

// ---------------- device scratch ----------------
__device__ float g_norm2[NMAX];
// fp16 weights: wih0[256x128] | whh0[256x64] | wih1 | whh1 | wih2 | whh2 (each 256x64)
__device__ __align__(16) __half g_w16[114688];

// ---------------- helpers ----------------
__device__ __forceinline__ void mma16(float* c, const unsigned* a, unsigned b0, unsigned b1) {
    asm volatile(
        "mma.sync.aligned.m16n8k16.row.col.f32.f16.f16.f32 "
        "{%0,%1,%2,%3}, {%4,%5,%6,%7}, {%8,%9}, {%0,%1,%2,%3};\n"
        : "+f"(c[0]), "+f"(c[1]), "+f"(c[2]), "+f"(c[3])
        : "r"(a[0]), "r"(a[1]), "r"(a[2]), "r"(a[3]), "r"(b0), "r"(b1));
}
__device__ __forceinline__ float tanha(float x) {
    float y;
    asm("tanh.approx.f32 %0, %1;" : "=f"(y) : "f"(x));
    return y;
}
__device__ __forceinline__ float fsig(float x) {          // sigmoid via 1-MUFU tanh
    return fmaf(0.5f, tanha(0.5f * x), 0.5f);
}
__device__ __forceinline__ float ftanh(float x) {         // accurate tanh (exp-based)
    float a = fabsf(x);
    float e = __expf(-2.0f * a);
    float t = __fdividef(1.0f - e, 1.0f + e);
    return copysignf(t, x);
}
__device__ __forceinline__ uint32_t smem_u32(const void* p) {
    uint32_t a;
    asm("{ .reg .u64 t; cvta.to.shared.u64 t, %1; cvt.u32.u64 %0, t; }" : "=r"(a) : "l"(p));
    return a;
}
__device__ __forceinline__ void cp16(uint32_t dst, const void* src) {
    asm volatile("cp.async.ca.shared.global [%0], [%1], 16;" :: "r"(dst), "l"(src) : "memory");
}
__device__ __forceinline__ void cp_commit() { asm volatile("cp.async.commit_group;" ::: "memory"); }
__device__ __forceinline__ void cp_wait1()  { asm volatile("cp.async.wait_group 1;" ::: "memory"); }
__device__ __forceinline__ void cp_wait0()  { asm volatile("cp.async.wait_group 0;" ::: "memory"); }
__device__ __forceinline__ unsigned h2u(__half2 h) { return *(unsigned*)&h; }

// ---------------- SMEM layout (bytes) ----------------
// A: 128 rows x 200 halves (stride 400B)  -> 51200 B   (K=192 used)
// B: 2 buffers x (128 rows x 40 halves = 80B) -> 2 x 10240 B
// bsum: 256 floats
#define A_OFF     0
#define B_OFF     51200
#define BBUF_SZ   10240
#define BSUM_OFF  (B_OFF + 2 * BBUF_SZ)
#define SMEM_BYTES (BSUM_OFF + 1024)

// fp16 weight offsets (in halves): {wih0, whh0, wih1, whh1, wih2, whh2}
__constant__ int c_woff[6] = {0, 32768, 49152, 65536, 81920, 98304};

// ---------------- kernel 1: per-row squared norms + weight fp16 convert ----------------
__global__ void prep_kernel(const float* __restrict__ feat, int n, int nb_norm,
                            const float* __restrict__ wih0, const float* __restrict__ whh0,
                            const float* __restrict__ wih1, const float* __restrict__ whh1,
                            const float* __restrict__ wih2, const float* __restrict__ whh2) {
    if ((int)blockIdx.x < nb_norm) {
        int row = (blockIdx.x * blockDim.x + threadIdx.x) >> 4;
        int sl = threadIdx.x & 15;
        if (row >= n) return;
        float4 v = *(const float4*)(feat + (size_t)row * 64 + sl * 4);
        float s = v.x * v.x + v.y * v.y + v.z * v.z + v.w * v.w;
        #pragma unroll
        for (int o = 8; o; o >>= 1) s += __shfl_down_sync(0xffffffffu, s, o, 16);
        if (sl == 0) g_norm2[row] = s;
    } else {
        int i = (blockIdx.x - nb_norm) * blockDim.x + threadIdx.x;   // one float2 per thread
        if (i >= 57344) return;
        const float* srcs[6] = {wih0, whh0, wih1, whh1, wih2, whh2};
        int reg, off2;
        if (i < 16384) { reg = 0; off2 = i; }
        else { int t = i - 16384; reg = 1 + t / 8192; off2 = t - (reg - 1) * 8192; }
        float2 v = ((const float2*)srcs[reg])[off2];
        int base2 = (reg == 0) ? 0 : (16384 + (reg - 1) * 8192);
        ((__half2*)g_w16)[base2 + off2] = __floats2half2_rn(v.x, v.y);
    }
}

// ---------------- kernel 2: fused gather + 3-layer LSTM (fp16 m16n8k16 mma) ----------------
__global__ __launch_bounds__(256, 2) void lstm_kernel(
    const float* __restrict__ feature, const int* __restrict__ src,
    const float* __restrict__ h0, const float* __restrict__ c0,
    const float* __restrict__ bih0, const float* __restrict__ bhh0,
    const float* __restrict__ bih1, const float* __restrict__ bhh1,
    const float* __restrict__ bih2, const float* __restrict__ bhh2,
    float* __restrict__ out, int n)
{
    extern __shared__ char smem[];
    unsigned* Xw = (unsigned*)(smem + A_OFF);        // A as 32-bit words (2 halves each)
    float* bsum = (float*)(smem + BSUM_OFF);
    const uint32_t sbase = smem_u32(smem);

    const int tid = threadIdx.x;
    const int lane = tid & 31;
    const int warp = tid >> 5;
    const int wm = warp >> 1, wn = warp & 1;
    const int gid = lane >> 2, tig = lane & 3;
    const int m0w = wm * 32;
    const int m0 = blockIdx.x * 128;

    // staging role: thread -> (row, 32B half of 64B row)
    const int rp = tid >> 1;
    const int part = tid & 1;
    const int gP0 = (rp >> 5) * 64 + (rp & 31);      // global W row for pass 0
    const uint32_t bdst_local = (uint32_t)(rp * 80 + part * 32);

    const float* bihA[3] = {bih0, bih1, bih2};
    const float* bhhA[3] = {bhh0, bhh1, bhh2};
    const size_t nd = (size_t)n * 64;
    float* out_hs = out + nd;
    float* out_cs = out + 4 * nd;

    // ---- hoisted prologue: stage (l=0,p=0) chunks 0,1 ----
    {
        const __half* s0 = g_w16 + (size_t)gP0 * 128 + part * 16;
        uint32_t d0 = sbase + B_OFF + bdst_local;
        cp16(d0, s0); cp16(d0 + 16, s0 + 8);
        cp_commit();
        const __half* s1 = s0 + 32;
        uint32_t d1 = sbase + B_OFF + BBUF_SZ + bdst_local;
        cp16(d1, s1); cp16(d1 + 16, s1 + 8);
        cp_commit();
    }

    // ---- inline message passing: per half-warp argmax over 32 neighbors + row gather ----
    // Writes A columns k [0,64) (words 0..31 per row) as fp16.
    {
        const int sl = lane & 15;            // lane within 16-segment
        const int seg = lane >> 4;           // 0 or 1: which node of the pair
        #pragma unroll 2
        for (int i = 0; i < 8; i++) {
            const int m = warp * 16 + i * 2 + seg;
            const int node = m0 + m;
            const bool valid = node < n;     // uniform within segment
            int2 s2 = make_int2(0, 0);
            if (valid) s2 = *(const int2*)(src + (size_t)node * 32 + sl * 2);
            float n0 = g_norm2[s2.x];
            float n1 = g_norm2[s2.y];
            // local pick (first-max: strictly greater to prefer lower index)
            float bv = (n1 > n0) ? n1 : n0;
            int bj = (n1 > n0) ? (2 * sl + 1) : (2 * sl);
            int bs = (n1 > n0) ? s2.y : s2.x;
            #pragma unroll
            for (int o = 8; o; o >>= 1) {
                float ov = __shfl_down_sync(0xffffffffu, bv, o, 16);
                int oj = __shfl_down_sync(0xffffffffu, bj, o, 16);
                int os = __shfl_down_sync(0xffffffffu, bs, o, 16);
                if (ov > bv || (ov == bv && oj < bj)) { bv = ov; bj = oj; bs = os; }
            }
            bs = __shfl_sync(0xffffffffu, bs, 0, 16);   // segment broadcast
            float4 v = make_float4(0.f, 0.f, 0.f, 0.f);
            if (valid) v = *(const float4*)(feature + (size_t)bs * 64 + sl * 4);
            uint2 t;
            t.x = h2u(__floats2half2_rn(v.x, v.y));
            t.y = h2u(__floats2half2_rn(v.z, v.w));
            *(uint2*)(&Xw[m * 100 + sl * 2]) = t;
        }
    }

    // ---- stage A columns k [64,192): [feature | h0[0]] ----
    #pragma unroll 4
    for (int i = 0; i < 16; i++) {
        int idx = tid + (i << 8);            // 0..4095 = 128 rows x 32 quads
        int m = idx >> 5, k4 = (idx & 31) + 16;
        int node = m0 + m;
        float4 v = make_float4(0.f, 0.f, 0.f, 0.f);
        if (node < n) {
            size_t off = (size_t)node * 64;
            v = (k4 < 32) ? *(const float4*)(feature + off + (k4 - 16) * 4)
                          : *(const float4*)(h0 + off + (k4 - 32) * 4);
        }
        uint2 t;
        t.x = h2u(__floats2half2_rn(v.x, v.y));
        t.y = h2u(__floats2half2_rn(v.z, v.w));
        *(uint2*)(&Xw[m * 100 + k4 * 2]) = t;
    }

    for (int l = 0; l < 3; l++) {
        bsum[tid] = bihA[l][tid] + bhhA[l][tid];
        const int ncg = (l == 0) ? 6 : 4;

        for (int p = 0; p < 2; p++) {
            const int grow = gP0 + p * 32;

            if (!(l == 0 && p == 0)) {
                #pragma unroll 1
                for (int c = 0; c < 2; c++) {
                    const __half* wp; int rs, ko;
                    if (l == 0) { wp = g_w16 + c_woff[0]; rs = 128; ko = c * 32; }
                    else {
                        int reg = (c < 2) ? (2 * l) : (2 * l + 1);
                        wp = g_w16 + c_woff[reg]; rs = 64; ko = (c & 1) * 32;
                    }
                    const __half* srcw = wp + (size_t)grow * rs + ko + part * 16;
                    uint32_t dst = sbase + B_OFF + (c & 1) * BBUF_SZ + bdst_local;
                    cp16(dst, srcw); cp16(dst + 16, srcw + 8);
                    cp_commit();
                }
            }

            float acc[2][8][4];
            #pragma unroll
            for (int mf = 0; mf < 2; mf++)
                #pragma unroll
                for (int f = 0; f < 8; f++)
                    #pragma unroll
                    for (int q = 0; q < 4; q++) acc[mf][f][q] = 0.f;

            #pragma unroll 1
            for (int c = 0; c < ncg; c++) {
                if (c < ncg - 1) cp_wait1(); else cp_wait0();
                __syncthreads();

                const unsigned* Bw = (const unsigned*)(smem + B_OFF + (c & 1) * BBUF_SZ);
                const int kw = c * 16;                 // chunk base in words (32 halves)
                #pragma unroll
                for (int ks = 0; ks < 2; ks++) {
                    const int w0 = kw + ks * 8 + tig;
                    unsigned a[2][4];
                    #pragma unroll
                    for (int mf = 0; mf < 2; mf++) {
                        int r = m0w + mf * 16 + gid;
                        a[mf][0] = Xw[r * 100 + w0];
                        a[mf][1] = Xw[(r + 8) * 100 + w0];
                        a[mf][2] = Xw[r * 100 + w0 + 4];
                        a[mf][3] = Xw[(r + 8) * 100 + w0 + 4];
                    }
                    const int bw0 = ks * 8 + tig;
                    #pragma unroll
                    for (int f = 0; f < 8; f++) {
                        int nc = (f >> 1) * 32 + wn * 16 + (f & 1) * 8 + gid;
                        unsigned b0 = Bw[nc * 20 + bw0];
                        unsigned b1 = Bw[nc * 20 + bw0 + 4];
                        mma16(acc[0][f], a[0], b0, b1);
                        mma16(acc[1][f], a[1], b0, b1);
                    }
                }
                __syncthreads();

                // re-stage chunk c+2 into buffer (c+2)&1
                int c2 = c + 2;
                if (c2 < ncg) {
                    const __half* wp; int rs, ko;
                    if (l == 0) {
                        if (c2 < 4) { wp = g_w16 + c_woff[0]; rs = 128; ko = c2 * 32; }
                        else        { wp = g_w16 + c_woff[1]; rs = 64;  ko = (c2 - 4) * 32; }
                    } else {
                        int reg = (c2 < 2) ? (2 * l) : (2 * l + 1);
                        wp = g_w16 + c_woff[reg]; rs = 64; ko = (c2 & 1) * 32;
                    }
                    const __half* srcw = wp + (size_t)grow * rs + ko + part * 16;
                    uint32_t dst = sbase + B_OFF + (c2 & 1) * BBUF_SZ + bdst_local;
                    cp16(dst, srcw); cp16(dst + 16, srcw + 8);
                    cp_commit();
                }
            }

            // ---------------- epilogue for this pass ----------------
            {
                const float* cg = c0 + (size_t)l * nd;
                const float* h0n = h0 + (size_t)(l + 1) * nd;
                float* hs_l = out_hs + (size_t)l * nd;
                float* cs_l = out_cs + (size_t)l * nd;

                #pragma unroll
                for (int mf = 0; mf < 2; mf++)
                    #pragma unroll
                    for (int jf = 0; jf < 2; jf++) {
                        const int d0 = p * 32 + wn * 16 + jf * 8 + 2 * tig;
                        #pragma unroll
                        for (int rh = 0; rh < 2; rh++) {
                            const int row = m0w + mf * 16 + gid + rh * 8;
                            const int node = m0 + row;
                            const bool valid = node < n;
                            const size_t noff = (size_t)node * 64;
                            float2 cp2 = make_float2(0.f, 0.f);
                            if (valid) cp2 = *(const float2*)(cg + noff + d0);
                            float hv[2], cv[2];
                            #pragma unroll
                            for (int q = 0; q < 2; q++) {
                                const int pp = rh * 2 + q;
                                const int d = d0 + q;
                                float iv = acc[mf][0 + jf][pp] + bsum[d];
                                float fv = acc[mf][2 + jf][pp] + bsum[64 + d];
                                float gv = acc[mf][4 + jf][pp] + bsum[128 + d];
                                float ov = acc[mf][6 + jf][pp] + bsum[192 + d];
                                float cprev = q ? cp2.y : cp2.x;
                                float cn = fsig(fv) * cprev + fsig(iv) * ftanh(gv);
                                hv[q] = fsig(ov) * ftanh(cn);
                                cv[q] = cn;
                            }
                            if (valid) {
                                *(float2*)(hs_l + noff + d0) = make_float2(hv[0], hv[1]);
                                *(float2*)(cs_l + noff + d0) = make_float2(cv[0], cv[1]);
                                if (l == 2) *(float2*)(out + noff + d0) = make_float2(hv[0], hv[1]);
                            }
                            // A rebuild only after the layer's final pass
                            if (l < 2 && p == 1) {
                                Xw[row * 100 + (d0 >> 1)] = h2u(__floats2half2_rn(hv[0], hv[1]));
                                float2 hh = make_float2(0.f, 0.f);
                                if (valid) hh = *(const float2*)(h0n + noff + d0);
                                Xw[row * 100 + 32 + (d0 >> 1)] = h2u(__floats2half2_rn(hh.x, hh.y));
                                // pass-0 columns: reload h from global (CTA-coherent after syncs)
                                const int dp = d0 - 32;
                                float2 hp = make_float2(0.f, 0.f), h2v = make_float2(0.f, 0.f);
                                if (valid) {
                                    hp = *(const float2*)(hs_l + noff + dp);
                                    h2v = *(const float2*)(h0n + noff + dp);
                                }
                                Xw[row * 100 + (dp >> 1)]      = h2u(__floats2half2_rn(hp.x, hp.y));
                                Xw[row * 100 + 32 + (dp >> 1)] = h2u(__floats2half2_rn(h2v.x, h2v.y));
                            }
                        }
                    }
                __syncthreads();
            }
        }
    }
}

// ---------------- launch ----------------
extern "C" void kernel_launch(void* const* d_in, const int* in_sizes, int n_in,
                              void* d_out, int out_size) {
    const float* feature = (const float*)d_in[0];
    const int* src       = (const int*)d_in[1];
    const float* h0      = (const float*)d_in[2];
    const float* c0      = (const float*)d_in[3];
    const float* wih0    = (const float*)d_in[4];
    const float* whh0    = (const float*)d_in[5];
    const float* bih0    = (const float*)d_in[6];
    const float* bhh0    = (const float*)d_in[7];
    const float* wih1    = (const float*)d_in[8];
    const float* whh1    = (const float*)d_in[9];
    const float* bih1    = (const float*)d_in[10];
    const float* bhh1    = (const float*)d_in[11];
    const float* wih2    = (const float*)d_in[12];
    const float* whh2    = (const float*)d_in[13];
    const float* bih2    = (const float*)d_in[14];
    const float* bhh2    = (const float*)d_in[15];
    float* out = (float*)d_out;

    int n = in_sizes[0] / 64;

    cudaFuncSetAttribute(lstm_kernel, cudaFuncAttributeMaxDynamicSharedMemorySize, SMEM_BYTES);

    int nb_norm = (n * 16 + 255) / 256;
    prep_kernel<<<nb_norm + 224, 256>>>(feature, n, nb_norm,
                                        wih0, whh0, wih1, whh1, wih2, whh2);

    int lblocks = (n + 127) / 128;
    lstm_kernel<<<lblocks, 256, SMEM_BYTES>>>(
        feature, src, h0, c0,
        bih0, bhh0, bih1, bhh1, bih2, bhh2,
        out, n);
}

// round 14
// speedup vs baseline: 1.3034x; 1.0442x over previous
#include <cuda_runtime.h>
#include <cuda_fp16.h>
#include <cstdint>
#include <math.h>

#define NMAX 100000

// ---------------- device scratch ----------------
__device__ float g_norm2[NMAX];
// fp16 weights: wih0[256x128] | whh0[256x64] | wih1 | whh1 | wih2 | whh2 (each 256x64)
__device__ __align__(16) __half g_w16[114688];

// ---------------- helpers ----------------
__device__ __forceinline__ void mma16(float* c, const unsigned* a, unsigned b0, unsigned b1) {
    asm volatile(
        "mma.sync.aligned.m16n8k16.row.col.f32.f16.f16.f32 "
        "{%0,%1,%2,%3}, {%4,%5,%6,%7}, {%8,%9}, {%0,%1,%2,%3};\n"
        : "+f"(c[0]), "+f"(c[1]), "+f"(c[2]), "+f"(c[3])
        : "r"(a[0]), "r"(a[1]), "r"(a[2]), "r"(a[3]), "r"(b0), "r"(b1));
}
__device__ __forceinline__ float tanha(float x) {
    float y;
    asm("tanh.approx.f32 %0, %1;" : "=f"(y) : "f"(x));
    return y;
}
__device__ __forceinline__ float fsig(float x) {          // sigmoid via 1-MUFU tanh
    return fmaf(0.5f, tanha(0.5f * x), 0.5f);
}
__device__ __forceinline__ float ftanh(float x) {         // accurate tanh (exp-based)
    float a = fabsf(x);
    float e = __expf(-2.0f * a);
    float t = __fdividef(1.0f - e, 1.0f + e);
    return copysignf(t, x);
}
__device__ __forceinline__ uint32_t smem_u32(const void* p) {
    uint32_t a;
    asm("{ .reg .u64 t; cvta.to.shared.u64 t, %1; cvt.u32.u64 %0, t; }" : "=r"(a) : "l"(p));
    return a;
}
__device__ __forceinline__ void cp16(uint32_t dst, const void* src) {
    asm volatile("cp.async.ca.shared.global [%0], [%1], 16;" :: "r"(dst), "l"(src) : "memory");
}
__device__ __forceinline__ void cp_commit() { asm volatile("cp.async.commit_group;" ::: "memory"); }
__device__ __forceinline__ void cp_wait1()  { asm volatile("cp.async.wait_group 1;" ::: "memory"); }
__device__ __forceinline__ void cp_wait0()  { asm volatile("cp.async.wait_group 0;" ::: "memory"); }
__device__ __forceinline__ unsigned h2u(__half2 h) { return *(unsigned*)&h; }

// ---------------- SMEM layout (bytes) ----------------
// A: 128 rows x 200 halves (stride 400B)  -> 51200 B   (K=192 used)
// B: 2 buffers x (128 rows x 72 halves = 144B, K=64 chunk) -> 2 x 18432 B
// bsum: 256 floats
#define A_OFF     0
#define B_OFF     51200
#define BBUF_SZ   18432
#define BSUM_OFF  (B_OFF + 2 * BBUF_SZ)    // 88064
#define SMEM_BYTES (BSUM_OFF + 1024)       // 89088

// fp16 weight offsets (in halves): {wih0, whh0, wih1, whh1, wih2, whh2}
__constant__ int c_woff[6] = {0, 32768, 49152, 65536, 81920, 98304};

// ---------------- kernel 1: per-row squared norms + weight fp16 convert ----------------
__global__ void prep_kernel(const float* __restrict__ feat, int n, int nb_norm,
                            const float* __restrict__ wih0, const float* __restrict__ whh0,
                            const float* __restrict__ wih1, const float* __restrict__ whh1,
                            const float* __restrict__ wih2, const float* __restrict__ whh2) {
    if ((int)blockIdx.x < nb_norm) {
        int row = (blockIdx.x * blockDim.x + threadIdx.x) >> 4;
        int sl = threadIdx.x & 15;
        if (row >= n) return;
        float4 v = *(const float4*)(feat + (size_t)row * 64 + sl * 4);
        float s = v.x * v.x + v.y * v.y + v.z * v.z + v.w * v.w;
        #pragma unroll
        for (int o = 8; o; o >>= 1) s += __shfl_down_sync(0xffffffffu, s, o, 16);
        if (sl == 0) g_norm2[row] = s;
    } else {
        int i = (blockIdx.x - nb_norm) * blockDim.x + threadIdx.x;   // one float2 per thread
        if (i >= 57344) return;
        const float* srcs[6] = {wih0, whh0, wih1, whh1, wih2, whh2};
        int reg, off2;
        if (i < 16384) { reg = 0; off2 = i; }
        else { int t = i - 16384; reg = 1 + t / 8192; off2 = t - (reg - 1) * 8192; }
        float2 v = ((const float2*)srcs[reg])[off2];
        int base2 = (reg == 0) ? 0 : (16384 + (reg - 1) * 8192);
        ((__half2*)g_w16)[base2 + off2] = __floats2half2_rn(v.x, v.y);
    }
}

// ---------------- kernel 2: fused gather + 3-layer LSTM (fp16 mma, K64 chunks) ----------------
__global__ __launch_bounds__(256, 2) void lstm_kernel(
    const float* __restrict__ feature, const int* __restrict__ src,
    const float* __restrict__ h0, const float* __restrict__ c0,
    const float* __restrict__ bih0, const float* __restrict__ bhh0,
    const float* __restrict__ bih1, const float* __restrict__ bhh1,
    const float* __restrict__ bih2, const float* __restrict__ bhh2,
    float* __restrict__ out, int n)
{
    extern __shared__ char smem[];
    unsigned* Xw = (unsigned*)(smem + A_OFF);        // A as 32-bit words (2 halves each)
    float* bsum = (float*)(smem + BSUM_OFF);
    const uint32_t sbase = smem_u32(smem);

    const int tid = threadIdx.x;
    const int lane = tid & 31;
    const int warp = tid >> 5;
    const int wm = warp >> 1, wn = warp & 1;
    const int gid = lane >> 2, tig = lane & 3;
    const int m0w = wm * 32;
    const int m0 = blockIdx.x * 128;

    // staging role: thread -> (row, 64B half of 128B K64 row)
    const int rp = tid >> 1;
    const int part = tid & 1;
    const int gP0 = (rp >> 5) * 64 + (rp & 31);      // global W row for pass 0
    const uint32_t bdst_local = (uint32_t)(rp * 144 + part * 64);

    const float* bihA[3] = {bih0, bih1, bih2};
    const float* bhhA[3] = {bhh0, bhh1, bhh2};
    const size_t nd = (size_t)n * 64;
    float* out_hs = out + nd;
    float* out_cs = out + 4 * nd;

    // ---- hoisted prologue: stage (l=0,p=0) K64 chunks 0,1 (wih0 k[0,64),[64,128)) ----
    {
        const __half* s0 = g_w16 + (size_t)gP0 * 128 + part * 32;
        uint32_t d0 = sbase + B_OFF + bdst_local;
        #pragma unroll
        for (int q = 0; q < 4; q++) cp16(d0 + q * 16, s0 + q * 8);
        cp_commit();
        const __half* s1 = s0 + 64;
        uint32_t d1 = sbase + B_OFF + BBUF_SZ + bdst_local;
        #pragma unroll
        for (int q = 0; q < 4; q++) cp16(d1 + q * 16, s1 + q * 8);
        cp_commit();
    }

    // ---- inline message passing: per half-warp argmax over 32 neighbors + row gather ----
    {
        const int sl = lane & 15;
        const int seg = lane >> 4;
        #pragma unroll 2
        for (int i = 0; i < 8; i++) {
            const int m = warp * 16 + i * 2 + seg;
            const int node = m0 + m;
            const bool valid = node < n;
            int2 s2 = make_int2(0, 0);
            if (valid) s2 = *(const int2*)(src + (size_t)node * 32 + sl * 2);
            float n0 = g_norm2[s2.x];
            float n1 = g_norm2[s2.y];
            float bv = (n1 > n0) ? n1 : n0;
            int bj = (n1 > n0) ? (2 * sl + 1) : (2 * sl);
            int bs = (n1 > n0) ? s2.y : s2.x;
            #pragma unroll
            for (int o = 8; o; o >>= 1) {
                float ov = __shfl_down_sync(0xffffffffu, bv, o, 16);
                int oj = __shfl_down_sync(0xffffffffu, bj, o, 16);
                int os = __shfl_down_sync(0xffffffffu, bs, o, 16);
                if (ov > bv || (ov == bv && oj < bj)) { bv = ov; bj = oj; bs = os; }
            }
            bs = __shfl_sync(0xffffffffu, bs, 0, 16);
            float4 v = make_float4(0.f, 0.f, 0.f, 0.f);
            if (valid) v = *(const float4*)(feature + (size_t)bs * 64 + sl * 4);
            uint2 t;
            t.x = h2u(__floats2half2_rn(v.x, v.y));
            t.y = h2u(__floats2half2_rn(v.z, v.w));
            *(uint2*)(&Xw[m * 100 + sl * 2]) = t;
        }
    }

    // ---- stage A columns k [64,192): [feature | h0[0]] ----
    #pragma unroll 4
    for (int i = 0; i < 16; i++) {
        int idx = tid + (i << 8);
        int m = idx >> 5, k4 = (idx & 31) + 16;
        int node = m0 + m;
        float4 v = make_float4(0.f, 0.f, 0.f, 0.f);
        if (node < n) {
            size_t off = (size_t)node * 64;
            v = (k4 < 32) ? *(const float4*)(feature + off + (k4 - 16) * 4)
                          : *(const float4*)(h0 + off + (k4 - 32) * 4);
        }
        uint2 t;
        t.x = h2u(__floats2half2_rn(v.x, v.y));
        t.y = h2u(__floats2half2_rn(v.z, v.w));
        *(uint2*)(&Xw[m * 100 + k4 * 2]) = t;
    }

    for (int l = 0; l < 3; l++) {
        bsum[tid] = bihA[l][tid] + bhhA[l][tid];
        const int ncg = (l == 0) ? 3 : 2;            // K64 chunks per pass

        for (int p = 0; p < 2; p++) {
            const int grow = gP0 + p * 32;

            // prologue staging of chunks 0,1 (skip l=0,p=0: hoisted)
            if (!(l == 0 && p == 0)) {
                #pragma unroll 1
                for (int c = 0; c < 2; c++) {
                    const __half* wp; int rs, ko;
                    if (l == 0) { wp = g_w16 + c_woff[0]; rs = 128; ko = c * 64; }
                    else {
                        int reg = (c == 0) ? (2 * l) : (2 * l + 1);
                        wp = g_w16 + c_woff[reg]; rs = 64; ko = 0;
                    }
                    const __half* srcw = wp + (size_t)grow * rs + ko + part * 32;
                    uint32_t dst = sbase + B_OFF + (c & 1) * BBUF_SZ + bdst_local;
                    #pragma unroll
                    for (int q = 0; q < 4; q++) cp16(dst + q * 16, srcw + q * 8);
                    cp_commit();
                }
            }

            float acc[2][8][4];
            #pragma unroll
            for (int mf = 0; mf < 2; mf++)
                #pragma unroll
                for (int f = 0; f < 8; f++)
                    #pragma unroll
                    for (int q = 0; q < 4; q++) acc[mf][f][q] = 0.f;

            #pragma unroll 1
            for (int c = 0; c < ncg; c++) {
                if (c < ncg - 1) cp_wait1(); else cp_wait0();
                __syncthreads();

                const unsigned* Bw = (const unsigned*)(smem + B_OFF + (c & 1) * BBUF_SZ);
                const int kw = c * 32;                 // chunk base in A words (64 halves)
                #pragma unroll
                for (int ks = 0; ks < 4; ks++) {
                    const int w0 = kw + ks * 8 + tig;
                    unsigned a[2][4];
                    #pragma unroll
                    for (int mf = 0; mf < 2; mf++) {
                        int r = m0w + mf * 16 + gid;
                        a[mf][0] = Xw[r * 100 + w0];
                        a[mf][1] = Xw[(r + 8) * 100 + w0];
                        a[mf][2] = Xw[r * 100 + w0 + 4];
                        a[mf][3] = Xw[(r + 8) * 100 + w0 + 4];
                    }
                    const int bw0 = ks * 8 + tig;
                    #pragma unroll
                    for (int f = 0; f < 8; f++) {
                        int nc = (f >> 1) * 32 + wn * 16 + (f & 1) * 8 + gid;
                        unsigned b0 = Bw[nc * 36 + bw0];
                        unsigned b1 = Bw[nc * 36 + bw0 + 4];
                        mma16(acc[0][f], a[0], b0, b1);
                        mma16(acc[1][f], a[1], b0, b1);
                    }
                }
                __syncthreads();

                // re-stage chunk c+2 into buffer (c+2)&1 (only l=0: chunk 2 = whh0)
                int c2 = c + 2;
                if (c2 < ncg) {
                    const __half* srcw = g_w16 + c_woff[1] + (size_t)grow * 64 + part * 32;
                    uint32_t dst = sbase + B_OFF + (c2 & 1) * BBUF_SZ + bdst_local;
                    #pragma unroll
                    for (int q = 0; q < 4; q++) cp16(dst + q * 16, srcw + q * 8);
                    cp_commit();
                }
            }

            // ---------------- epilogue for this pass ----------------
            {
                const float* cg = c0 + (size_t)l * nd;
                const float* h0n = h0 + (size_t)(l + 1) * nd;
                float* hs_l = out_hs + (size_t)l * nd;
                float* cs_l = out_cs + (size_t)l * nd;

                #pragma unroll
                for (int mf = 0; mf < 2; mf++)
                    #pragma unroll
                    for (int jf = 0; jf < 2; jf++) {
                        const int d0 = p * 32 + wn * 16 + jf * 8 + 2 * tig;
                        #pragma unroll
                        for (int rh = 0; rh < 2; rh++) {
                            const int row = m0w + mf * 16 + gid + rh * 8;
                            const int node = m0 + row;
                            const bool valid = node < n;
                            const size_t noff = (size_t)node * 64;
                            float2 cp2 = make_float2(0.f, 0.f);
                            if (valid) cp2 = *(const float2*)(cg + noff + d0);
                            float hv[2], cv[2];
                            #pragma unroll
                            for (int q = 0; q < 2; q++) {
                                const int pp = rh * 2 + q;
                                const int d = d0 + q;
                                float iv = acc[mf][0 + jf][pp] + bsum[d];
                                float fv = acc[mf][2 + jf][pp] + bsum[64 + d];
                                float gv = acc[mf][4 + jf][pp] + bsum[128 + d];
                                float ov = acc[mf][6 + jf][pp] + bsum[192 + d];
                                float cprev = q ? cp2.y : cp2.x;
                                float cn = fsig(fv) * cprev + fsig(iv) * ftanh(gv);
                                hv[q] = fsig(ov) * ftanh(cn);
                                cv[q] = cn;
                            }
                            if (valid) {
                                *(float2*)(hs_l + noff + d0) = make_float2(hv[0], hv[1]);
                                *(float2*)(cs_l + noff + d0) = make_float2(cv[0], cv[1]);
                                if (l == 2) *(float2*)(out + noff + d0) = make_float2(hv[0], hv[1]);
                            }
                            // A rebuild only after the layer's final pass
                            if (l < 2 && p == 1) {
                                Xw[row * 100 + (d0 >> 1)] = h2u(__floats2half2_rn(hv[0], hv[1]));
                                float2 hh = make_float2(0.f, 0.f);
                                if (valid) hh = *(const float2*)(h0n + noff + d0);
                                Xw[row * 100 + 32 + (d0 >> 1)] = h2u(__floats2half2_rn(hh.x, hh.y));
                                const int dp = d0 - 32;
                                float2 hp = make_float2(0.f, 0.f), h2v = make_float2(0.f, 0.f);
                                if (valid) {
                                    hp = *(const float2*)(hs_l + noff + dp);
                                    h2v = *(const float2*)(h0n + noff + dp);
                                }
                                Xw[row * 100 + (dp >> 1)]      = h2u(__floats2half2_rn(hp.x, hp.y));
                                Xw[row * 100 + 32 + (dp >> 1)] = h2u(__floats2half2_rn(h2v.x, h2v.y));
                            }
                        }
                    }
                __syncthreads();
            }
        }
    }
}

// ---------------- launch ----------------
extern "C" void kernel_launch(void* const* d_in, const int* in_sizes, int n_in,
                              void* d_out, int out_size) {
    const float* feature = (const float*)d_in[0];
    const int* src       = (const int*)d_in[1];
    const float* h0      = (const float*)d_in[2];
    const float* c0      = (const float*)d_in[3];
    const float* wih0    = (const float*)d_in[4];
    const float* whh0    = (const float*)d_in[5];
    const float* bih0    = (const float*)d_in[6];
    const float* bhh0    = (const float*)d_in[7];
    const float* wih1    = (const float*)d_in[8];
    const float* whh1    = (const float*)d_in[9];
    const float* bih1    = (const float*)d_in[10];
    const float* bhh1    = (const float*)d_in[11];
    const float* wih2    = (const float*)d_in[12];
    const float* whh2    = (const float*)d_in[13];
    const float* bih2    = (const float*)d_in[14];
    const float* bhh2    = (const float*)d_in[15];
    float* out = (float*)d_out;

    int n = in_sizes[0] / 64;

    cudaFuncSetAttribute(lstm_kernel, cudaFuncAttributeMaxDynamicSharedMemorySize, SMEM_BYTES);

    int nb_norm = (n * 16 + 255) / 256;
    prep_kernel<<<nb_norm + 224, 256>>>(feature, n, nb_norm,
                                        wih0, whh0, wih1, whh1, wih2, whh2);

    int lblocks = (n + 127) / 128;
    lstm_kernel<<<lblocks, 256, SMEM_BYTES>>>(
        feature, src, h0, c0,
        bih0, bhh0, bih1, bhh1, bih2, bhh2,
        out, n);
}